// round 12
// baseline (speedup 1.0000x reference)
#include <cuda_runtime.h>

#define NB 128
#define NN 128
#define INNER 40
#define OUTD 512
#define FCH 41
#define ROWF (NN * FCH)          // 5248 floats per (b,i) row
#define ROWQ (ROWF / 4)          // 1312 float4

typedef unsigned long long ull;

// Scratch (allocation-free: device globals)
__device__ float g_S0[NB * NN * INNER];     // row sums over j of g[b,i,j,f], f<40
__device__ float g_core0[NB * NN * INNER];  // diagonal attrs g[b,i,i,f], f<40
__device__ float g_bonds[NB * NN * NN];     // g[b,i,j,40] laid out [b][i][j]
__device__ float g_cores[3 * NB * NN * INNER]; // [d][b][grp][f][n32]

// ---------------- helpers ----------------
__device__ __forceinline__ ull pk(float a, float b) {
    ull r;
    asm("mov.b64 %0, {%1,%2};" : "=l"(r) : "f"(a), "f"(b));
    return r;
}
__device__ __forceinline__ ull fma2(ull a, ull b, ull c) {
    ull d;
    asm("fma.rn.f32x2 %0, %1, %2, %3;" : "=l"(d) : "l"(a), "l"(b), "l"(c));
    return d;
}
__device__ __forceinline__ float lo64(ull v) { return __uint_as_float((unsigned)v); }
__device__ __forceinline__ float hi64(ull v) { return __uint_as_float((unsigned)(v >> 32)); }

struct ull2x { ull x, y; };

__device__ __forceinline__ float wred_max(float v) {
#pragma unroll
    for (int o = 16; o; o >>= 1) v = fmaxf(v, __shfl_xor_sync(0xffffffffu, v, o));
    return v;
}
__device__ __forceinline__ float wred_sum(float v) {
#pragma unroll
    for (int o = 16; o; o >>= 1) v += __shfl_xor_sync(0xffffffffu, v, o);
    return v;
}

// ---------------- kernel 1: streaming row reduction, 2 rows per block ----------------
// (unchanged — 62.3-62.6 us @ ~72% DRAM; near practical r+w roofline)
__global__ void __launch_bounds__(FCH * 8, 3) k_rowsum(const float* __restrict__ g,
                                                       float* __restrict__ out) {
    const int pr   = blockIdx.x;         // row pair 0..8191
    const int row0 = pr * 2;
    const int t    = threadIdx.x;        // 0..327
    const float4* base = reinterpret_cast<const float4*>(g + (long long)row0 * ROWF);

    __shared__ float s_flat[2][FCH * 32];   // per-row channel partials

    if (t < 2) reinterpret_cast<float4*>(out)[row0 + t] = make_float4(0.f, 0.f, 0.f, 0.f);

    float4 v[8];
#pragma unroll
    for (int s = 0; s < 4; s++) {
        v[s]     = base[t + 328 * s];
        v[4 + s] = base[ROWQ + t + 328 * s];
    }

    int f4[4], jb[4];
#pragma unroll
    for (int k = 0; k < 4; k++) {
        int e = 4 * t + k;
        f4[k] = e % FCH;
        jb[k] = e / FCH;
    }

#pragma unroll
    for (int r = 0; r < 2; r++) {
        const int row = row0 + r;
        const int i   = row & (NN - 1);
        float* brow = g_bonds + row * NN;
        float acc0 = 0.f, acc1 = 0.f, acc2 = 0.f, acc3 = 0.f;
#pragma unroll
        for (int s = 0; s < 4; s++) {
            float4 x = v[4 * r + s];
            const int j0 = 32 * s;
            if (f4[0] == FCH - 1) brow[jb[0] + j0] = x.x;
            else { acc0 += x.x; if (jb[0] + j0 == i) g_core0[row * INNER + f4[0]] = x.x; }
            if (f4[1] == FCH - 1) brow[jb[1] + j0] = x.y;
            else { acc1 += x.y; if (jb[1] + j0 == i) g_core0[row * INNER + f4[1]] = x.y; }
            if (f4[2] == FCH - 1) brow[jb[2] + j0] = x.z;
            else { acc2 += x.z; if (jb[2] + j0 == i) g_core0[row * INNER + f4[2]] = x.z; }
            if (f4[3] == FCH - 1) brow[jb[3] + j0] = x.w;
            else { acc3 += x.w; if (jb[3] + j0 == i) g_core0[row * INNER + f4[3]] = x.w; }
        }
        *reinterpret_cast<float4*>(&s_flat[r][4 * t]) = make_float4(acc0, acc1, acc2, acc3);
    }
    __syncthreads();

    if (t < INNER) {
        float t0 = 0.f, t1 = 0.f;
#pragma unroll
        for (int m = 0; m < 32; m++) {     // stride 41 mod 32 = 9, gcd(9,32)=1 -> conflict-free
            t0 += s_flat[0][t + FCH * m];
            t1 += s_flat[1][t + FCH * m];
        }
        g_S0[row0 * INNER + t]       = t0;
        g_S0[(row0 + 1) * INNER + t] = t1;
    }
}

// ---------------- kernel 2: compute the three cores (unchanged) ----------------
__global__ void __launch_bounds__(128) k_cores(
    const float* __restrict__ Wi,   // (3,40,40)
    const float* __restrict__ bi)   // (3,1,40)
{
    const int b   = blockIdx.x;
    const int grp = blockIdx.y;
    const int i0  = grp * 32;
    const int tid = threadIdx.x;
    const int warp = tid >> 5, lane = tid & 31;

    __shared__ float shA[32][INNER + 1];   // S0, later pre2
    __shared__ float shC0[32][INNER + 1];  // core0
    __shared__ float shc[32];
    __shared__ float shcp[4][32];
    __shared__ float cores[3][INNER][32];

    for (int idx = tid; idx < 32 * INNER; idx += 128) {
        int n = idx / INNER, f2 = idx % INNER;
        int row = b * NN + i0 + n;
        shA[n][f2] = g_S0[row * INNER + f2];
        float cv = g_core0[row * INNER + f2];
        shC0[n][f2] = cv;
        cores[0][f2][n] = cv;
    }
    {
        const float* bb = g_bonds + (b * NN) * NN + i0 + lane;
        float cp = 0.f;
#pragma unroll 8
        for (int m = 0; m < 32; m++)
            cp += bb[(warp + 4 * m) * NN];
        shcp[warp][lane] = cp;
    }
    __syncthreads();
    if (tid < 32)
        shc[tid] = 1.0f + shcp[0][tid] + shcp[1][tid] + shcp[2][tid] + shcp[3][tid];
    __syncthreads();

    for (int idx = tid; idx < INNER * 32; idx += 128) {
        int fp = idx >> 5, n = idx & 31;
        float s = bi[INNER + fp];
#pragma unroll
        for (int f2 = 0; f2 < INNER; f2++)
            s = fmaf(shA[n][f2], Wi[INNER * INNER + f2 * INNER + fp], s);
        cores[1][fp][n] = s;
    }
    __syncthreads();

    for (int idx = tid; idx < INNER * 32; idx += 128) {
        int f2 = idx >> 5, n = idx & 31;
        float d1 = cores[1][f2][n] - shC0[n][f2];
        shA[n][f2] = fmaf(shc[n], d1, shA[n][f2]);
    }
    __syncthreads();

    for (int idx = tid; idx < INNER * 32; idx += 128) {
        int fp = idx >> 5, n = idx & 31;
        float s = bi[2 * INNER + fp];
#pragma unroll
        for (int f2 = 0; f2 < INNER; f2++)
            s = fmaf(shA[n][f2], Wi[2 * INNER * INNER + f2 * INNER + fp], s);
        cores[2][fp][n] = s;
    }
    __syncthreads();

    for (int idx = tid; idx < 3 * 32 * INNER; idx += 128) {
        int n = idx & 31;
        int f2 = (idx >> 5) % INNER;
        int d = idx / (32 * INNER);
        g_cores[((d * NB + b) * 4 + grp) * (32 * INNER) + f2 * 32 + n] = cores[d][f2][n];
    }
}

// ---------------- kernel 3: logits GEMM + softmax + fp, one depth per LAUNCH ----------------
// grid (128, 4), block 256 = 2 teams x 128 threads. Team tm: nodes [16tm, 16tm+16),
// 2 passes of 8. Thread u (0..127) owns cols 4u..4u+3 (exactly covers 512).
// Half-size tiles + 24 warps/SM (launch_bounds 256,3) attack the measured
// latency-bound regime (occ 20%, no pipe >50%). Per-depth launch keeps the 80KB
// W slab L1-resident across all concurrent blocks.
template <int D>
__global__ void __launch_bounds__(256, 3) k_gemm(
    const float* __restrict__ Wo,   // (3,40,512)
    const float* __restrict__ bo,   // (3,1,512)
    float* __restrict__ out)        // (128,512)
{
    const int b   = blockIdx.x;
    const int grp = blockIdx.y;
    const int tid = threadIdx.x;
    const int warp = tid >> 5, lane = tid & 31;  // warp 0..7
    const int tm  = tid >> 7;       // team 0/1 (warps 4tm..4tm+3)
    const int u   = tid & 127;      // col-quad owner

    __shared__ __align__(16) ull sC[INNER * 32];  // pk(core,core), flat [f][n]
    __shared__ float redm[8][8];
    __shared__ float reds[8][8];

    // stage cores, pre-duplicated
    {
        const float* src = g_cores + ((D * NB + b) * 4 + grp) * (32 * INNER);
        for (int idx = tid; idx < INNER * 32; idx += 256) {
            float v = src[idx];
            sC[idx] = pk(v, v);
        }
    }
    __syncthreads();

    const float* Wd = Wo + D * (INNER * OUTD) + (u << 2);
    const ull2x ba = *reinterpret_cast<const ull2x*>(bo + D * OUTD + (u << 2));

    float fpa[4] = {0.f, 0.f, 0.f, 0.f};

#pragma unroll 1
    for (int p = 0; p < 2; p++) {
        const int bn = tm * 16 + p * 8;  // first node of this pass

        ull acc[8][2];
#pragma unroll
        for (int n = 0; n < 8; n++) { acc[n][0] = ba.x; acc[n][1] = ba.y; }

        const float* wp = Wd;
        const ull2x* cp2 = reinterpret_cast<const ull2x*>(sC + bn);
#pragma unroll 4
        for (int f2 = 0; f2 < INNER; f2++, wp += OUTD, cp2 += 16) {
            ull2x wa = *reinterpret_cast<const ull2x*>(wp);   // cols 4u..4u+3
            ull2x c01 = cp2[0], c23 = cp2[1], c45 = cp2[2], c67 = cp2[3];

            acc[0][0] = fma2(c01.x, wa.x, acc[0][0]);  acc[0][1] = fma2(c01.x, wa.y, acc[0][1]);
            acc[1][0] = fma2(c01.y, wa.x, acc[1][0]);  acc[1][1] = fma2(c01.y, wa.y, acc[1][1]);
            acc[2][0] = fma2(c23.x, wa.x, acc[2][0]);  acc[2][1] = fma2(c23.x, wa.y, acc[2][1]);
            acc[3][0] = fma2(c23.y, wa.x, acc[3][0]);  acc[3][1] = fma2(c23.y, wa.y, acc[3][1]);
            acc[4][0] = fma2(c45.x, wa.x, acc[4][0]);  acc[4][1] = fma2(c45.x, wa.y, acc[4][1]);
            acc[5][0] = fma2(c45.y, wa.x, acc[5][0]);  acc[5][1] = fma2(c45.y, wa.y, acc[5][1]);
            acc[6][0] = fma2(c67.x, wa.x, acc[6][0]);  acc[6][1] = fma2(c67.x, wa.y, acc[6][1]);
            acc[7][0] = fma2(c67.y, wa.x, acc[7][0]);  acc[7][1] = fma2(c67.y, wa.y, acc[7][1]);
        }

        // unpack: node n, cols 4u..4u+3
        float v[8][4];
#pragma unroll
        for (int n = 0; n < 8; n++) {
            v[n][0] = lo64(acc[n][0]); v[n][1] = hi64(acc[n][0]);
            v[n][2] = lo64(acc[n][1]); v[n][3] = hi64(acc[n][1]);
        }

        // per-node max over 512 outputs (4 local -> warp -> team of 4 warps)
#pragma unroll
        for (int n = 0; n < 8; n++) {
            float m = fmaxf(fmaxf(v[n][0], v[n][1]), fmaxf(v[n][2], v[n][3]));
            m = wred_max(m);
            if (lane == 0) redm[warp][n] = m;
        }
        __syncthreads();
        float M[8];
#pragma unroll
        for (int n = 0; n < 8; n++)
            M[n] = fmaxf(fmaxf(redm[4 * tm][n],     redm[4 * tm + 1][n]),
                         fmaxf(redm[4 * tm + 2][n], redm[4 * tm + 3][n]));

        // exp + per-node sum
#pragma unroll
        for (int n = 0; n < 8; n++) {
            float s = 0.f;
#pragma unroll
            for (int k = 0; k < 4; k++) {
                v[n][k] = __expf(v[n][k] - M[n]);
                s += v[n][k];
            }
            s = wred_sum(s);
            if (lane == 0) reds[warp][n] = s;
        }
        __syncthreads();

#pragma unroll
        for (int n = 0; n < 8; n++) {
            float R = 1.0f / (reds[4 * tm][n] + reds[4 * tm + 1][n] +
                              reds[4 * tm + 2][n] + reds[4 * tm + 3][n]);
#pragma unroll
            for (int k = 0; k < 4; k++) fpa[k] += v[n][k] * R;
        }
        __syncthreads();   // protect redm/reds before next pass overwrites
    }

    float* po = out + b * OUTD + (u << 2);
#pragma unroll
    for (int k = 0; k < 4; k++) atomicAdd(po + k, fpa[k]);
}

// ---------------- launch ----------------
extern "C" void kernel_launch(void* const* d_in, const int* in_sizes, int n_in,
                              void* d_out, int out_size) {
    const float* graph = (const float*)d_in[0];
    const float* Wi    = (const float*)d_in[1];
    const float* bi    = (const float*)d_in[2];
    const float* Wo    = (const float*)d_in[3];
    const float* bo    = (const float*)d_in[4];
    float* out = (float*)d_out;

    k_rowsum<<<NB * NN / 2, FCH * 8>>>(graph, out);
    dim3 gc(NB, 4);
    k_cores<<<gc, 128>>>(Wi, bi);
    dim3 gg(NB, 4);
    k_gemm<0><<<gg, 256>>>(Wo, bo, out);
    k_gemm<1><<<gg, 256>>>(Wo, bo, out);
    k_gemm<2><<<gg, 256>>>(Wo, bo, out);
}

// round 16
// speedup vs baseline: 1.1724x; 1.1724x over previous
#include <cuda_runtime.h>

#define NB 128
#define NN 128
#define INNER 40
#define OUTD 512
#define FCH 41
#define ROWF (NN * FCH)          // 5248 floats per (b,i) row
#define ROWQ (ROWF / 4)          // 1312 float4

typedef unsigned long long ull;

// Scratch (allocation-free: device globals)
__device__ float g_S0[NB * NN * INNER];     // row sums over j of g[b,i,j,f], f<40
__device__ float g_core0[NB * NN * INNER];  // diagonal attrs g[b,i,i,f], f<40
__device__ float g_bonds[NB * NN * NN];     // g[b,i,j,40] laid out [b][i][j]
__device__ float g_cores[3 * NB * NN * INNER]; // [d][b][grp][f][n32]

// ---------------- helpers ----------------
__device__ __forceinline__ ull pk(float a, float b) {
    ull r;
    asm("mov.b64 %0, {%1,%2};" : "=l"(r) : "f"(a), "f"(b));
    return r;
}
// IN-PLACE f32x2 FMA: accumulator tied to output reg ("+l") -> no marshal MOVs.
__device__ __forceinline__ void fma2ip(ull& c, ull a, ull b) {
    asm("fma.rn.f32x2 %0, %1, %2, %0;" : "+l"(c) : "l"(a), "l"(b));
}
__device__ __forceinline__ float lo64(ull v) { return __uint_as_float((unsigned)v); }
__device__ __forceinline__ float hi64(ull v) { return __uint_as_float((unsigned)(v >> 32)); }

struct ull2x { ull x, y; };

__device__ __forceinline__ float wred_max(float v) {
#pragma unroll
    for (int o = 16; o; o >>= 1) v = fmaxf(v, __shfl_xor_sync(0xffffffffu, v, o));
    return v;
}
__device__ __forceinline__ float wred_sum(float v) {
#pragma unroll
    for (int o = 16; o; o >>= 1) v += __shfl_xor_sync(0xffffffffu, v, o);
    return v;
}

// ---------------- kernel 1: streaming row reduction, 2 rows per block ----------------
// (unchanged — 62.3-62.6 us @ ~72% DRAM; near practical r+w roofline)
__global__ void __launch_bounds__(FCH * 8, 3) k_rowsum(const float* __restrict__ g,
                                                       float* __restrict__ out) {
    const int pr   = blockIdx.x;         // row pair 0..8191
    const int row0 = pr * 2;
    const int t    = threadIdx.x;        // 0..327
    const float4* base = reinterpret_cast<const float4*>(g + (long long)row0 * ROWF);

    __shared__ float s_flat[2][FCH * 32];   // per-row channel partials

    if (t < 2) reinterpret_cast<float4*>(out)[row0 + t] = make_float4(0.f, 0.f, 0.f, 0.f);

    float4 v[8];
#pragma unroll
    for (int s = 0; s < 4; s++) {
        v[s]     = base[t + 328 * s];
        v[4 + s] = base[ROWQ + t + 328 * s];
    }

    int f4[4], jb[4];
#pragma unroll
    for (int k = 0; k < 4; k++) {
        int e = 4 * t + k;
        f4[k] = e % FCH;
        jb[k] = e / FCH;
    }

#pragma unroll
    for (int r = 0; r < 2; r++) {
        const int row = row0 + r;
        const int i   = row & (NN - 1);
        float* brow = g_bonds + row * NN;
        float acc0 = 0.f, acc1 = 0.f, acc2 = 0.f, acc3 = 0.f;
#pragma unroll
        for (int s = 0; s < 4; s++) {
            float4 x = v[4 * r + s];
            const int j0 = 32 * s;
            if (f4[0] == FCH - 1) brow[jb[0] + j0] = x.x;
            else { acc0 += x.x; if (jb[0] + j0 == i) g_core0[row * INNER + f4[0]] = x.x; }
            if (f4[1] == FCH - 1) brow[jb[1] + j0] = x.y;
            else { acc1 += x.y; if (jb[1] + j0 == i) g_core0[row * INNER + f4[1]] = x.y; }
            if (f4[2] == FCH - 1) brow[jb[2] + j0] = x.z;
            else { acc2 += x.z; if (jb[2] + j0 == i) g_core0[row * INNER + f4[2]] = x.z; }
            if (f4[3] == FCH - 1) brow[jb[3] + j0] = x.w;
            else { acc3 += x.w; if (jb[3] + j0 == i) g_core0[row * INNER + f4[3]] = x.w; }
        }
        *reinterpret_cast<float4*>(&s_flat[r][4 * t]) = make_float4(acc0, acc1, acc2, acc3);
    }
    __syncthreads();

    if (t < INNER) {
        float t0 = 0.f, t1 = 0.f;
#pragma unroll
        for (int m = 0; m < 32; m++) {     // stride 41 mod 32 = 9, gcd(9,32)=1 -> conflict-free
            t0 += s_flat[0][t + FCH * m];
            t1 += s_flat[1][t + FCH * m];
        }
        g_S0[row0 * INNER + t]       = t0;
        g_S0[(row0 + 1) * INNER + t] = t1;
    }
}

// ---------------- kernel 2: compute the three cores (unchanged) ----------------
__global__ void __launch_bounds__(128) k_cores(
    const float* __restrict__ Wi,   // (3,40,40)
    const float* __restrict__ bi)   // (3,1,40)
{
    const int b   = blockIdx.x;
    const int grp = blockIdx.y;
    const int i0  = grp * 32;
    const int tid = threadIdx.x;
    const int warp = tid >> 5, lane = tid & 31;

    __shared__ float shA[32][INNER + 1];   // S0, later pre2
    __shared__ float shC0[32][INNER + 1];  // core0
    __shared__ float shc[32];
    __shared__ float shcp[4][32];
    __shared__ float cores[3][INNER][32];

    for (int idx = tid; idx < 32 * INNER; idx += 128) {
        int n = idx / INNER, f2 = idx % INNER;
        int row = b * NN + i0 + n;
        shA[n][f2] = g_S0[row * INNER + f2];
        float cv = g_core0[row * INNER + f2];
        shC0[n][f2] = cv;
        cores[0][f2][n] = cv;
    }
    {
        const float* bb = g_bonds + (b * NN) * NN + i0 + lane;
        float cp = 0.f;
#pragma unroll 8
        for (int m = 0; m < 32; m++)
            cp += bb[(warp + 4 * m) * NN];
        shcp[warp][lane] = cp;
    }
    __syncthreads();
    if (tid < 32)
        shc[tid] = 1.0f + shcp[0][tid] + shcp[1][tid] + shcp[2][tid] + shcp[3][tid];
    __syncthreads();

    for (int idx = tid; idx < INNER * 32; idx += 128) {
        int fp = idx >> 5, n = idx & 31;
        float s = bi[INNER + fp];
#pragma unroll
        for (int f2 = 0; f2 < INNER; f2++)
            s = fmaf(shA[n][f2], Wi[INNER * INNER + f2 * INNER + fp], s);
        cores[1][fp][n] = s;
    }
    __syncthreads();

    for (int idx = tid; idx < INNER * 32; idx += 128) {
        int f2 = idx >> 5, n = idx & 31;
        float d1 = cores[1][f2][n] - shC0[n][f2];
        shA[n][f2] = fmaf(shc[n], d1, shA[n][f2]);
    }
    __syncthreads();

    for (int idx = tid; idx < INNER * 32; idx += 128) {
        int fp = idx >> 5, n = idx & 31;
        float s = bi[2 * INNER + fp];
#pragma unroll
        for (int f2 = 0; f2 < INNER; f2++)
            s = fmaf(shA[n][f2], Wi[2 * INNER * INNER + f2 * INNER + fp], s);
        cores[2][fp][n] = s;
    }
    __syncthreads();

    for (int idx = tid; idx < 3 * 32 * INNER; idx += 128) {
        int n = idx & 31;
        int f2 = (idx >> 5) % INNER;
        int d = idx / (32 * INNER);
        g_cores[((d * NB + b) * 4 + grp) * (32 * INNER) + f2 * 32 + n] = cores[d][f2][n];
    }
}

// ---------------- kernel 3: logits GEMM + softmax + fp ----------------
// grid (128, 4, 3), block 128 = 2 teams x 64 threads (round-10 best config).
// Team tm handles nodes [16*tm, 16*tm+16) in 2 passes of 8 nodes.
// Thread u (0..63) owns cols {4u..4u+3} U {256+4u..256+4u+3}.
// ONLY change vs round 10: in-place fma2ip accumulators (no asm marshal MOVs).
__global__ void __launch_bounds__(128, 4) k_gemm(
    const float* __restrict__ Wo,   // (3,40,512)
    const float* __restrict__ bo,   // (3,1,512)
    float* __restrict__ out)        // (128,512)
{
    const int b   = blockIdx.x;
    const int grp = blockIdx.y;
    const int d   = blockIdx.z;
    const int tid = threadIdx.x;
    const int warp = tid >> 5, lane = tid & 31;
    const int tm  = tid >> 6;       // team 0/1
    const int u   = tid & 63;       // col-octet owner

    __shared__ __align__(16) ull sC[INNER * 32];  // pk(core,core), flat [f][n]
    __shared__ float redm[4][8];
    __shared__ float reds[4][8];

    // stage cores, pre-duplicated
    {
        const float* src = g_cores + ((d * NB + b) * 4 + grp) * (32 * INNER);
        for (int idx = tid; idx < INNER * 32; idx += 128) {
            float v = src[idx];
            sC[idx] = pk(v, v);
        }
    }
    __syncthreads();

    const float* Wd = Wo + d * (INNER * OUTD) + (u << 2);
    const ull2x ba = *reinterpret_cast<const ull2x*>(bo + d * OUTD + (u << 2));
    const ull2x bb = *reinterpret_cast<const ull2x*>(bo + d * OUTD + 256 + (u << 2));

    float fpa[8] = {0.f, 0.f, 0.f, 0.f, 0.f, 0.f, 0.f, 0.f};

#pragma unroll 1
    for (int p = 0; p < 2; p++) {
        const int bn = tm * 16 + p * 8;  // first node of this pass

        ull acc[8][4];
#pragma unroll
        for (int n = 0; n < 8; n++) {
            acc[n][0] = ba.x; acc[n][1] = ba.y;
            acc[n][2] = bb.x; acc[n][3] = bb.y;
        }

        const float* wp = Wd;
        const ull2x* cp2 = reinterpret_cast<const ull2x*>(sC + bn);
#pragma unroll 4
        for (int f2 = 0; f2 < INNER; f2++, wp += OUTD, cp2 += 16) {
            ull2x wa = *reinterpret_cast<const ull2x*>(wp);        // cols 4u..4u+3
            ull2x wb = *reinterpret_cast<const ull2x*>(wp + 256);  // cols 256+4u..
            ull2x c01 = cp2[0], c23 = cp2[1], c45 = cp2[2], c67 = cp2[3];

            fma2ip(acc[0][0], c01.x, wa.x); fma2ip(acc[0][1], c01.x, wa.y);
            fma2ip(acc[0][2], c01.x, wb.x); fma2ip(acc[0][3], c01.x, wb.y);
            fma2ip(acc[1][0], c01.y, wa.x); fma2ip(acc[1][1], c01.y, wa.y);
            fma2ip(acc[1][2], c01.y, wb.x); fma2ip(acc[1][3], c01.y, wb.y);
            fma2ip(acc[2][0], c23.x, wa.x); fma2ip(acc[2][1], c23.x, wa.y);
            fma2ip(acc[2][2], c23.x, wb.x); fma2ip(acc[2][3], c23.x, wb.y);
            fma2ip(acc[3][0], c23.y, wa.x); fma2ip(acc[3][1], c23.y, wa.y);
            fma2ip(acc[3][2], c23.y, wb.x); fma2ip(acc[3][3], c23.y, wb.y);
            fma2ip(acc[4][0], c45.x, wa.x); fma2ip(acc[4][1], c45.x, wa.y);
            fma2ip(acc[4][2], c45.x, wb.x); fma2ip(acc[4][3], c45.x, wb.y);
            fma2ip(acc[5][0], c45.y, wa.x); fma2ip(acc[5][1], c45.y, wa.y);
            fma2ip(acc[5][2], c45.y, wb.x); fma2ip(acc[5][3], c45.y, wb.y);
            fma2ip(acc[6][0], c67.x, wa.x); fma2ip(acc[6][1], c67.x, wa.y);
            fma2ip(acc[6][2], c67.x, wb.x); fma2ip(acc[6][3], c67.x, wb.y);
            fma2ip(acc[7][0], c67.y, wa.x); fma2ip(acc[7][1], c67.y, wa.y);
            fma2ip(acc[7][2], c67.y, wb.x); fma2ip(acc[7][3], c67.y, wb.y);
        }

        // unpack: node n, 8 cols {4u+0..3, 256+4u+0..3}
        float v[8][8];
#pragma unroll
        for (int n = 0; n < 8; n++) {
            v[n][0] = lo64(acc[n][0]); v[n][1] = hi64(acc[n][0]);
            v[n][2] = lo64(acc[n][1]); v[n][3] = hi64(acc[n][1]);
            v[n][4] = lo64(acc[n][2]); v[n][5] = hi64(acc[n][2]);
            v[n][6] = lo64(acc[n][3]); v[n][7] = hi64(acc[n][3]);
        }

        // per-node max over 512 outputs (8 local -> warp -> team of 2 warps)
#pragma unroll
        for (int n = 0; n < 8; n++) {
            float m = v[n][0];
#pragma unroll
            for (int k = 1; k < 8; k++) m = fmaxf(m, v[n][k]);
            m = wred_max(m);
            if (lane == 0) redm[warp][n] = m;
        }
        __syncthreads();
        float M[8];
#pragma unroll
        for (int n = 0; n < 8; n++)
            M[n] = fmaxf(redm[2 * tm][n], redm[2 * tm + 1][n]);

        // exp + per-node sum
#pragma unroll
        for (int n = 0; n < 8; n++) {
            float s = 0.f;
#pragma unroll
            for (int k = 0; k < 8; k++) {
                v[n][k] = __expf(v[n][k] - M[n]);
                s += v[n][k];
            }
            s = wred_sum(s);
            if (lane == 0) reds[warp][n] = s;
        }
        __syncthreads();

#pragma unroll
        for (int n = 0; n < 8; n++) {
            float R = 1.0f / (reds[2 * tm][n] + reds[2 * tm + 1][n]);
#pragma unroll
            for (int k = 0; k < 8; k++) fpa[k] += v[n][k] * R;
        }
        __syncthreads();   // protect redm/reds before next pass overwrites
    }

    float* po = out + b * OUTD + (u << 2);
#pragma unroll
    for (int k = 0; k < 4; k++) atomicAdd(po + k, fpa[k]);
#pragma unroll
    for (int k = 0; k < 4; k++) atomicAdd(po + 256 + k, fpa[4 + k]);
}

// ---------------- launch ----------------
extern "C" void kernel_launch(void* const* d_in, const int* in_sizes, int n_in,
                              void* d_out, int out_size) {
    const float* graph = (const float*)d_in[0];
    const float* Wi    = (const float*)d_in[1];
    const float* bi    = (const float*)d_in[2];
    const float* Wo    = (const float*)d_in[3];
    const float* bo    = (const float*)d_in[4];
    float* out = (float*)d_out;

    k_rowsum<<<NB * NN / 2, FCH * 8>>>(graph, out);
    dim3 gc(NB, 4);
    k_cores<<<gc, 128>>>(Wi, bi);
    dim3 gg(NB, 4, 3);
    k_gemm<<<gg, 128>>>(Wo, bo, out);
}